// round 15
// baseline (speedup 1.0000x reference)
#include <cuda_runtime.h>
#include <cuda_bf16.h>
#include <cuda_fp16.h>
#include <math.h>
#include <stdint.h>

// ---------------------------------------------------------------------------
// Problem constants
// ---------------------------------------------------------------------------
#define Nn   32768
#define Dd   128
#define Hh   2
#define HDm  64
#define Ee   262144
#define Mm   131072
#define NGg  32
#define PW   896          // 128(Q2)+128(K2)+256(Q3)+256(K3)+128(Qm)
#define PB   768          // bf16 mirror width (Q2|K2|Q3|K3)
#define KSL  32
#define TMt  2
#define LAM3 0.5f
#define EPSV 1e-5f

// ---------------------------------------------------------------------------
// Scratch
// ---------------------------------------------------------------------------
__device__ __align__(256) __nv_bfloat16 g_Gh[(size_t)Nn * Dd];  // bf16 LN output
__device__ float g_mu[Nn];
__device__ float g_rstd[Nn];
__device__ float g_P[(size_t)Nn * PW];                          // Qm cols (768..) fp32
__device__ __align__(256) __nv_bfloat16 g_Pb[(size_t)Nn * PB];  // bf16 cols 0..767
__device__ __align__(256) __half g_Uh[(size_t)Nn * PW];         // f16 grad accumulator
__device__ __align__(256) __nv_bfloat16 g_WcatB[PW * Dd];       // bf16 [j][d] fwd GEMM
__device__ __align__(256) __half g_WcatHT[Dd * PW];             // f16 [d][j] bwd GEMM
__device__ __nv_bfloat16 g_TtH[TMt * Hh * 2 * HDm];             // bf16 Ttau mirror
__device__ float g_Km[Hh * KSL * HDm];     // [h][k][z]
__device__ float g_KmT[Hh * HDm * KSL];    // [h][z][k]
__device__ float g_s2[(size_t)Ee * Hh];    // exp(s2)
__device__ float g_Z2[Nn * Hh];
__device__ float g_qk[(size_t)Mm * 4];
__device__ float g_tv[(size_t)Mm * 4];
__device__ float g_s3[(size_t)Mm * Hh];    // exp(s3)
__device__ float g_Z3[Nn * Hh];
__device__ float g_Lm[Nn * Hh];

// ---------------------------------------------------------------------------
// Helpers
// ---------------------------------------------------------------------------
__device__ __forceinline__ float wsum32(float v) {
#pragma unroll
    for (int m = 16; m > 0; m >>= 1) v += __shfl_xor_sync(0xffffffffu, v, m);
    return v;
}
__device__ __forceinline__ float wsum16(float v) {
#pragma unroll
    for (int m = 8; m > 0; m >>= 1) v += __shfl_xor_sync(0xffffffffu, v, m);
    return v;
}
__device__ __forceinline__ float wsum8(float v) {
#pragma unroll
    for (int m = 4; m > 0; m >>= 1) v += __shfl_xor_sync(0xffffffffu, v, m);
    return v;
}
__device__ __forceinline__ void red_add_v4h(__half* addr, uint32_t a, uint32_t b,
                                            uint32_t c, uint32_t d) {
    asm volatile("red.global.add.noftz.v4.f16x2 [%0], {%1, %2, %3, %4};"
                 :: "l"(addr), "r"(a), "r"(b), "r"(c), "r"(d) : "memory");
}
__device__ __forceinline__ uint32_t pack2h(float a, float b) {
    __half2 h = __floats2half2_rn(a, b);
    return *reinterpret_cast<uint32_t*>(&h);
}
__device__ __forceinline__ void ld4bf(const __nv_bfloat16* p, float* f) {
    uint2 r = *(const uint2*)p;
    __nv_bfloat162 h0 = *reinterpret_cast<const __nv_bfloat162*>(&r.x);
    __nv_bfloat162 h1 = *reinterpret_cast<const __nv_bfloat162*>(&r.y);
    float2 a = __bfloat1622float2(h0), b = __bfloat1622float2(h1);
    f[0] = a.x; f[1] = a.y; f[2] = b.x; f[3] = b.y;
}
__device__ __forceinline__ void ld8bf(const __nv_bfloat16* p, float* f) {
    uint4 r = *(const uint4*)p;
    __nv_bfloat162 h0 = *reinterpret_cast<const __nv_bfloat162*>(&r.x);
    __nv_bfloat162 h1 = *reinterpret_cast<const __nv_bfloat162*>(&r.y);
    __nv_bfloat162 h2 = *reinterpret_cast<const __nv_bfloat162*>(&r.z);
    __nv_bfloat162 h3 = *reinterpret_cast<const __nv_bfloat162*>(&r.w);
    float2 a = __bfloat1622float2(h0), b = __bfloat1622float2(h1);
    float2 c = __bfloat1622float2(h2), d = __bfloat1622float2(h3);
    f[0] = a.x; f[1] = a.y; f[2] = b.x; f[3] = b.y;
    f[4] = c.x; f[5] = c.y; f[6] = d.x; f[7] = d.y;
}
__device__ __forceinline__ void ldsm4(uint32_t* r, uint32_t addr) {
    asm volatile("ldmatrix.sync.aligned.m8n8.x4.shared.b16 {%0,%1,%2,%3}, [%4];"
                 : "=r"(r[0]), "=r"(r[1]), "=r"(r[2]), "=r"(r[3]) : "r"(addr));
}
__device__ __forceinline__ void mma16(float* c, const uint32_t* a, const uint32_t* b, __half) {
    asm volatile(
        "mma.sync.aligned.m16n8k16.row.col.f32.f16.f16.f32 "
        "{%0,%1,%2,%3}, {%4,%5,%6,%7}, {%8,%9}, {%0,%1,%2,%3};"
        : "+f"(c[0]), "+f"(c[1]), "+f"(c[2]), "+f"(c[3])
        : "r"(a[0]), "r"(a[1]), "r"(a[2]), "r"(a[3]), "r"(b[0]), "r"(b[1]));
}
__device__ __forceinline__ void mma16(float* c, const uint32_t* a, const uint32_t* b, __nv_bfloat16) {
    asm volatile(
        "mma.sync.aligned.m16n8k16.row.col.f32.bf16.bf16.f32 "
        "{%0,%1,%2,%3}, {%4,%5,%6,%7}, {%8,%9}, {%0,%1,%2,%3};"
        : "+f"(c[0]), "+f"(c[1]), "+f"(c[2]), "+f"(c[3])
        : "r"(a[0]), "r"(a[1]), "r"(a[2]), "r"(a[3]), "r"(b[0]), "r"(b[1]));
}
#define CP16(dst, src) \
    asm volatile("cp.async.cg.shared.global [%0], [%1], 16;" \
                 :: "r"(dst), "l"(src) : "memory")
#define CP_COMMIT() asm volatile("cp.async.commit_group;" ::: "memory")
#define CP_WAIT2()  asm volatile("cp.async.wait_group 2;" ::: "memory")
#define CP_WAIT0()  asm volatile("cp.async.wait_group 0;" ::: "memory")

// ---------------------------------------------------------------------------
// LayerNorm forward -> bf16 G
// ---------------------------------------------------------------------------
__global__ void k_ln(const float* __restrict__ X, const float* __restrict__ gamma,
                     const float* __restrict__ beta) {
    int w = (blockIdx.x * blockDim.x + threadIdx.x) >> 5;
    int lane = threadIdx.x & 31;
    if (w >= Nn) return;
    const float4 x = *(const float4*)(X + (size_t)w * Dd + lane * 4);
    float s = x.x + x.y + x.z + x.w;
    float mu = wsum32(s) * (1.0f / Dd);
    float4 xc = make_float4(x.x - mu, x.y - mu, x.z - mu, x.w - mu);
    float v = xc.x * xc.x + xc.y * xc.y + xc.z * xc.z + xc.w * xc.w;
    v = wsum32(v) * (1.0f / Dd);
    float rstd = rsqrtf(v + EPSV);
    const float4 g4 = *(const float4*)(gamma + lane * 4);
    const float4 b4 = *(const float4*)(beta + lane * 4);
    float Gx = g4.x * xc.x * rstd + b4.x;
    float Gy = g4.y * xc.y * rstd + b4.y;
    float Gz = g4.z * xc.z * rstd + b4.z;
    float Gw = g4.w * xc.w * rstd + b4.w;
    uint2 pk;
    __nv_bfloat162 h0 = __floats2bfloat162_rn(Gx, Gy);
    __nv_bfloat162 h1 = __floats2bfloat162_rn(Gz, Gw);
    pk.x = *reinterpret_cast<uint32_t*>(&h0);
    pk.y = *reinterpret_cast<uint32_t*>(&h1);
    *(uint2*)(g_Gh + (size_t)w * Dd + lane * 4) = pk;
    if (lane == 0) { g_mu[w] = mu; g_rstd[w] = rstd; }
}

// ---------------------------------------------------------------------------
// Stacked weights + Ttau mirror
// ---------------------------------------------------------------------------
__global__ void k_wcat(const float* __restrict__ WQ2, const float* __restrict__ WK2,
                       const float* __restrict__ WQ3, const float* __restrict__ WK3,
                       const float* __restrict__ WQm, const float* __restrict__ Ttau) {
    int idx = blockIdx.x * blockDim.x + threadIdx.x;
    if (idx < TMt * Hh * 2 * HDm) g_TtH[idx] = __float2bfloat16(Ttau[idx]);
    if (idx >= PW * Dd) return;
    int j = idx / Dd, d = idx - j * Dd;
    float v;
    if (j < 128)      v = WQ2[j * Dd + d];
    else if (j < 256) v = WK2[(j - 128) * Dd + d];
    else if (j < 512) v = WQ3[(j - 256) * Dd + d];
    else if (j < 768) v = WK3[(j - 512) * Dd + d];
    else              v = WQm[(j - 768) * Dd + d];
    g_WcatB[j * Dd + d] = __float2bfloat16(v);
    g_WcatHT[d * PW + j] = __float2half(v);
}

// ---------------------------------------------------------------------------
// Km = B_mem @ W_Km^T per head
// ---------------------------------------------------------------------------
__global__ void k_km(const float* __restrict__ Bm, const float* __restrict__ WKm) {
    int idx = blockIdx.x * blockDim.x + threadIdx.x;
    if (idx >= Hh * KSL * HDm) return;
    int h = idx / (KSL * HDm);
    int k = (idx / HDm) % KSL;
    int z = idx % HDm;
    const float* b = Bm + k * Dd;
    const float* w = WKm + (h * HDm + z) * Dd;
    float acc = 0.f;
#pragma unroll 8
    for (int d = 0; d < Dd; d++) acc += b[d] * w[d];
    g_Km[idx] = acc;
    g_KmT[(h * HDm + z) * KSL + k] = acc;
}

// ---------------------------------------------------------------------------
// Forward 4-stage cp.async pipelined bf16 GEMM
// ---------------------------------------------------------------------------
#define STG_ELEM (128 * 24)
__global__ void __launch_bounds__(256)
k_gemmF(const __nv_bfloat16* __restrict__ A, int lda,
        const __nv_bfloat16* __restrict__ Bt, int ldb,
        float* __restrict__ C, int ldc, int Kdim,
        __nv_bfloat16* __restrict__ Cb) {
    extern __shared__ __align__(16) char smRaw[];
    __nv_bfloat16* As = (__nv_bfloat16*)smRaw;
    __nv_bfloat16* Bs = As + 4 * STG_ELEM;
    int tid = threadIdx.x;
    int warp = tid >> 5, lane = tid & 31;
    int g = lane >> 2, tg = lane & 3;
    int wm = (warp >> 2) * 64;
    int wn = (warp & 3) * 32;
    int row0 = blockIdx.y * 128, col0 = blockIdx.x * 128;
    int lr = tid >> 1;
    int lc = (tid & 1) * 8;
    const __nv_bfloat16* Ap = A + (size_t)(row0 + lr) * lda + lc;
    const __nv_bfloat16* Bp = Bt + (size_t)(col0 + lr) * ldb + lc;

    uint32_t aSt[4], bSt[4], aLd[4], bLd[4];
#pragma unroll
    for (int s = 0; s < 4; s++) {
        aSt[s] = (uint32_t)__cvta_generic_to_shared(As + (s * 128 + lr) * 24 + lc);
        bSt[s] = (uint32_t)__cvta_generic_to_shared(Bs + (s * 128 + lr) * 24 + lc);
        aLd[s] = (uint32_t)__cvta_generic_to_shared(
            As + (s * 128 + wm + (lane & 15)) * 24 + (lane >> 4) * 8);
        bLd[s] = (uint32_t)__cvta_generic_to_shared(
            Bs + (s * 128 + wn + ((lane >> 4) & 1) * 8 + (lane & 7)) * 24 +
            ((lane >> 3) & 1) * 8);
    }
    const uint32_t pit = 48;

    float acc[16][4];
#pragma unroll
    for (int i = 0; i < 16; i++)
#pragma unroll
        for (int j = 0; j < 4; j++) acc[i][j] = 0.f;

    int nk = Kdim >> 4;
#pragma unroll
    for (int s = 0; s < 3; s++) {
        if (s < nk) {
            CP16(aSt[s], Ap + s * 16);
            CP16(bSt[s], Bp + s * 16);
        }
        CP_COMMIT();
    }

    for (int kt = 0; kt < nk; kt++) {
        CP_WAIT2();
        __syncthreads();
        int cur = kt & 3;
        uint32_t af[4][4], bq[2][4];
#pragma unroll
        for (int mi = 0; mi < 4; mi++)
            ldsm4(af[mi], aLd[cur] + mi * 16 * pit);
#pragma unroll
        for (int ni2 = 0; ni2 < 2; ni2++)
            ldsm4(bq[ni2], bLd[cur] + ni2 * 16 * pit);
#pragma unroll
        for (int mi = 0; mi < 4; mi++)
#pragma unroll
            for (int ni = 0; ni < 4; ni++)
                mma16(acc[mi * 4 + ni], af[mi], &bq[ni >> 1][(ni & 1) * 2],
                      __nv_bfloat16{});
        int nx = kt + 3;
        if (nx < nk) {
            int sl = nx & 3;
            CP16(aSt[sl], Ap + nx * 16);
            CP16(bSt[sl], Bp + nx * 16);
        }
        CP_COMMIT();
    }

    bool asbf = (col0 < PB);
#pragma unroll
    for (int mi = 0; mi < 4; mi++)
#pragma unroll
        for (int ni = 0; ni < 4; ni++) {
            float* c = acc[mi * 4 + ni];
            int r = row0 + wm + mi * 16 + g;
            int col = col0 + wn + ni * 8 + 2 * tg;
            if (asbf) {
                *(__nv_bfloat162*)(Cb + (size_t)r * PB + col) =
                    __floats2bfloat162_rn(c[0], c[1]);
                *(__nv_bfloat162*)(Cb + (size_t)(r + 8) * PB + col) =
                    __floats2bfloat162_rn(c[2], c[3]);
            } else {
                *(float2*)(C + (size_t)r * ldc + col) = make_float2(c[0], c[1]);
                *(float2*)(C + (size_t)(r + 8) * ldc + col) = make_float2(c[2], c[3]);
            }
        }
}

// ---------------------------------------------------------------------------
// Backward GEMM fused with final update. dG staged as f16 in REUSED pipeline
// smem (pitch 136 -> conflict-free). Dynamic smem = 48KB only -> 2 CTAs/SM.
// ---------------------------------------------------------------------------
#define DGP 136
__global__ void __launch_bounds__(256)
k_gemmB_fin(const __half* __restrict__ A, int lda,
            const __half* __restrict__ Bt, int ldb, int Kdim,
            const float* __restrict__ X, const float* __restrict__ gamma,
            const float* __restrict__ step, const int* __restrict__ batch,
            float* __restrict__ out, float* __restrict__ Eg) {
    extern __shared__ __align__(16) char smRaw[];
    __half* As = (__half*)smRaw;
    __half* Bs = As + 4 * STG_ELEM;
    __shared__ float bins[NGg];
    int tid = threadIdx.x;
    int warp = tid >> 5, lane = tid & 31;
    int g = lane >> 2, tg = lane & 3;
    int wm = (warp >> 2) * 64;
    int wn = (warp & 3) * 32;
    int row0 = blockIdx.y * 128;
    int lr = tid >> 1;
    int lc = (tid & 1) * 8;
    const __half* Ap = A + (size_t)(row0 + lr) * lda + lc;
    const __half* Bp = Bt + (size_t)lr * ldb + lc;

    if (tid < NGg) bins[tid] = 0.f;

    uint32_t aSt[4], bSt[4], aLd[4], bLd[4];
#pragma unroll
    for (int s = 0; s < 4; s++) {
        aSt[s] = (uint32_t)__cvta_generic_to_shared(As + (s * 128 + lr) * 24 + lc);
        bSt[s] = (uint32_t)__cvta_generic_to_shared(Bs + (s * 128 + lr) * 24 + lc);
        aLd[s] = (uint32_t)__cvta_generic_to_shared(
            As + (s * 128 + wm + (lane & 15)) * 24 + (lane >> 4) * 8);
        bLd[s] = (uint32_t)__cvta_generic_to_shared(
            Bs + (s * 128 + wn + ((lane >> 4) & 1) * 8 + (lane & 7)) * 24 +
            ((lane >> 3) & 1) * 8);
    }
    const uint32_t pit = 48;

    float acc[16][4];
#pragma unroll
    for (int i = 0; i < 16; i++)
#pragma unroll
        for (int j = 0; j < 4; j++) acc[i][j] = 0.f;

    int nk = Kdim >> 4;
#pragma unroll
    for (int s = 0; s < 3; s++) {
        if (s < nk) {
            CP16(aSt[s], Ap + s * 16);
            CP16(bSt[s], Bp + s * 16);
        }
        CP_COMMIT();
    }

    for (int kt = 0; kt < nk; kt++) {
        CP_WAIT2();
        __syncthreads();
        int cur = kt & 3;
        uint32_t af[4][4], bq[2][4];
#pragma unroll
        for (int mi = 0; mi < 4; mi++)
            ldsm4(af[mi], aLd[cur] + mi * 16 * pit);
#pragma unroll
        for (int ni2 = 0; ni2 < 2; ni2++)
            ldsm4(bq[ni2], bLd[cur] + ni2 * 16 * pit);
#pragma unroll
        for (int mi = 0; mi < 4; mi++)
#pragma unroll
            for (int ni = 0; ni < 4; ni++)
                mma16(acc[mi * 4 + ni], af[mi], &bq[ni >> 1][(ni & 1) * 2], __half{});
        int nx = kt + 3;
        if (nx < nk) {
            int sl = nx & 3;
            CP16(aSt[sl], Ap + nx * 16);
            CP16(bSt[sl], Bp + nx * 16);
        }
        CP_COMMIT();
    }

    // Reuse pipeline smem for the dG tile (f16, padded pitch).
    CP_WAIT0();
    __syncthreads();
    __half* dGs = (__half*)smRaw;            // [128][DGP]
#pragma unroll
    for (int mi = 0; mi < 4; mi++)
#pragma unroll
        for (int ni = 0; ni < 4; ni++) {
            float* c = acc[mi * 4 + ni];
            int r = wm + mi * 16 + g;
            int col = wn + ni * 8 + 2 * tg;
            *(__half2*)(dGs + r * DGP + col) = __floats2half2_rn(c[0], c[1]);
            *(__half2*)(dGs + (r + 8) * DGP + col) = __floats2half2_rn(c[2], c[3]);
        }
    __syncthreads();

    // fused final: warp handles rows warp*16 .. warp*16+15
    const float4 gm = *(const float4*)(gamma + lane * 4);
    float stp = step[0];
    for (int i = 0; i < 16; i++) {
        int r = warp * 16 + i;
        int w = row0 + r;
        const float4 x = *(const float4*)(X + (size_t)w * Dd + lane * 4);
        float dgf[4];
        {
            uint2 hv = *(const uint2*)(dGs + r * DGP + lane * 4);
            __half2 a = *reinterpret_cast<__half2*>(&hv.x);
            __half2 b = *reinterpret_cast<__half2*>(&hv.y);
            float2 fa = __half22float2(a), fb = __half22float2(b);
            dgf[0] = fa.x; dgf[1] = fa.y; dgf[2] = fb.x; dgf[3] = fb.y;
        }
        float mu = g_mu[w], rstd = g_rstd[w];
        float4 xh = make_float4((x.x - mu) * rstd, (x.y - mu) * rstd,
                                (x.z - mu) * rstd, (x.w - mu) * rstd);
        float4 dxh = make_float4(dgf[0] * gm.x, dgf[1] * gm.y,
                                 dgf[2] * gm.z, dgf[3] * gm.w);
        float S1 = wsum32(dxh.x + dxh.y + dxh.z + dxh.w) * (1.0f / Dd);
        float S2 = wsum32(dxh.x * xh.x + dxh.y * xh.y + dxh.z * xh.z + dxh.w * xh.w) * (1.0f / Dd);
        float ss = wsum32(x.x * x.x + x.y * x.y + x.z * x.z + x.w * x.w);
        float4 gr;
        gr.x = x.x + rstd * (dxh.x - S1 - xh.x * S2);
        gr.y = x.y + rstd * (dxh.y - S1 - xh.y * S2);
        gr.z = x.z + rstd * (dxh.z - S1 - xh.z * S2);
        gr.w = x.w + rstd * (dxh.w - S1 - xh.w * S2);
        float gss = wsum32(gr.x * gr.x + gr.y * gr.y + gr.z * gr.z + gr.w * gr.w);
        float sc1 = 1.0f / fmaxf(sqrtf(gss), 1.0f);
        float st = stp * sc1;
        float4 xn = make_float4(x.x - st * gr.x, x.y - st * gr.y,
                                x.z - st * gr.z, x.w - st * gr.w);
        float sn = wsum32(xn.x * xn.x + xn.y * xn.y + xn.z * xn.z + xn.w * xn.w);
        float sc2 = 10.0f / fmaxf(sqrtf(sn), 10.0f);
        float4 o = make_float4(xn.x * sc2, xn.y * sc2, xn.z * sc2, xn.w * sc2);
        *(float4*)(out + (size_t)w * Dd + lane * 4) = o;
        if (lane == 0) {
            float e = 0.5f * ss;
            float z0 = g_Z2[w * 2], z1 = g_Z2[w * 2 + 1];
            e -= (z0 > 0.f ? logf(z0) : 0.f) + (z1 > 0.f ? logf(z1) : 0.f);
            float y0 = g_Z3[w * 2], y1 = g_Z3[w * 2 + 1];
            e -= LAM3 * ((y0 > 0.f ? logf(y0) : 0.f) + (y1 > 0.f ? logf(y1) : 0.f));
            e -= g_Lm[w * 2] + g_Lm[w * 2 + 1];
            atomicAdd(&bins[batch[w]], e);
        }
    }
    __syncthreads();
    if (tid < NGg) atomicAdd(&Eg[tid], bins[tid]);
}

// ---------------------------------------------------------------------------
// Pair forward
// ---------------------------------------------------------------------------
__global__ void k_pair_fwd(const int* __restrict__ c2, const int* __restrict__ u2,
                           const float* __restrict__ a2) {
    int e = (blockIdx.x * 256 + threadIdx.x) >> 5;
    int lane = threadIdx.x & 31;
    if (e >= Ee) return;
    int c = c2[e], u = u2[e];
    float q[4], k[4];
    ld4bf(g_Pb + (size_t)c * PB + lane * 4, q);
    ld4bf(g_Pb + (size_t)u * PB + 128 + lane * 4, k);
    float part = q[0] * k[0] + q[1] * k[1] + q[2] * k[2] + q[3] * k[3];
    part = wsum16(part);
    int h = lane >> 4;
    if ((lane & 15) == 0) {
        float s = part * 0.125f + a2[e * 2 + h];
        float ex = __expf(s);
        g_s2[(size_t)e * 2 + h] = ex;
        atomicAdd(&g_Z2[c * 2 + h], ex);
    }
}

// Pair backward
__global__ void k_pair_bwd(const int* __restrict__ c2, const int* __restrict__ u2) {
    int e = (blockIdx.x * 256 + threadIdx.x) >> 5;
    int lane = threadIdx.x & 31;
    if (e >= Ee) return;
    int c = c2[e], u = u2[e];
    float2 ex = *(const float2*)&g_s2[(size_t)e * 2];
    float2 Z  = *(const float2*)&g_Z2[c * 2];
    float wt0 = -0.125f * ex.x / Z.x;
    float wt1 = -0.125f * ex.y / Z.y;
    int dk_side = lane >> 4;
    int i = lane & 15;
    float wt = (i >> 3) ? wt1 : wt0;
    const __nv_bfloat16* src = dk_side ? (g_Pb + (size_t)c * PB + i * 8)
                                       : (g_Pb + (size_t)u * PB + 128 + i * 8);
    float v[8];
    ld8bf(src, v);
    __half* dst = dk_side ? (g_Uh + (size_t)u * PW + 128 + i * 8)
                          : (g_Uh + (size_t)c * PW + i * 8);
    red_add_v4h(dst, pack2h(wt*v[0],wt*v[1]), pack2h(wt*v[2],wt*v[3]),
                     pack2h(wt*v[4],wt*v[5]), pack2h(wt*v[6],wt*v[7]));
}

// ---------------------------------------------------------------------------
// Motif forward
// ---------------------------------------------------------------------------
__global__ void k_motif_fwd(const int* __restrict__ c3, const int* __restrict__ u3,
                            const int* __restrict__ v3, const int* __restrict__ tt,
                            const float* __restrict__ Ttau) {
    int m = (blockIdx.x * 256 + threadIdx.x) >> 5;
    int lane = threadIdx.x & 31;
    if (m >= Mm) return;
    int c = c3[m], ua = u3[m], vb = v3[m], t = tt[m];
    int off = lane * 8;
    float q[8], ku[8], kv[8];
    ld8bf(g_Pb + (size_t)c  * PB + 256 + off, q);
    ld8bf(g_Pb + (size_t)ua * PB + 512 + off, ku);
    ld8bf(g_Pb + (size_t)vb * PB + 512 + off, kv);
    const float* tp = Ttau + t * 256 + off;
    float qk = 0.f, tv = 0.f;
#pragma unroll
    for (int i = 0; i < 8; i++) {
        qk += q[i] * ku[i];
        tv += tp[i] * kv[i];
    }
    qk = wsum8(qk);
    tv = wsum8(tv);
    int g = lane >> 3;
    if ((lane & 7) == 0) {
        g_qk[(size_t)m * 4 + g] = qk;
        g_tv[(size_t)m * 4 + g] = tv;
    }
    float qk0 = __shfl_sync(0xffffffffu, qk, 0),  tv0 = __shfl_sync(0xffffffffu, tv, 0);
    float qk1 = __shfl_sync(0xffffffffu, qk, 8),  tv1 = __shfl_sync(0xffffffffu, tv, 8);
    float qk2 = __shfl_sync(0xffffffffu, qk, 16), tv2 = __shfl_sync(0xffffffffu, tv, 16);
    float qk3 = __shfl_sync(0xffffffffu, qk, 24), tv3 = __shfl_sync(0xffffffffu, tv, 24);
    if (lane < 2) {
        float s3 = (lane == 0) ? (qk0 * tv0 + qk1 * tv1) * (1.0f / 64)
                               : (qk2 * tv2 + qk3 * tv3) * (1.0f / 64);
        float ex = __expf(s3);
        g_s3[(size_t)m * 2 + lane] = ex;
        atomicAdd(&g_Z3[c * 2 + lane], ex);
    }
}

// Motif backward
__global__ void k_motif_bwd(const int* __restrict__ c3, const int* __restrict__ u3,
                            const int* __restrict__ v3, const int* __restrict__ tt) {
    int m = (blockIdx.x * 256 + threadIdx.x) >> 5;
    int lane = threadIdx.x & 31;
    if (m >= Mm) return;
    int c = c3[m], ua = u3[m], vb = v3[m], t = tt[m];
    int g = lane >> 3;
    int h = g >> 1;
    float2 ex = *(const float2*)&g_s3[(size_t)m * 2];
    float2 Z  = *(const float2*)&g_Z3[c * 2];
    float p = h ? (ex.y / Z.y) : (ex.x / Z.x);
    float gg = -LAM3 * p * (1.0f / 64);
    float cA = gg * g_tv[(size_t)m * 4 + g];
    float cB = gg * g_qk[(size_t)m * 4 + g];
    int off = lane * 8;
    float q[8], ku[8], tp8[8];
    ld8bf(g_Pb + (size_t)c  * PB + 256 + off, q);
    ld8bf(g_Pb + (size_t)ua * PB + 512 + off, ku);
    ld8bf(g_TtH + t * 256 + off, tp8);
    __half* dq  = g_Uh + (size_t)c  * PW + 256 + off;
    __half* dku = g_Uh + (size_t)ua * PW + 512 + off;
    __half* dkv = g_Uh + (size_t)vb * PW + 512 + off;
    red_add_v4h(dq,  pack2h(cA*ku[0],cA*ku[1]), pack2h(cA*ku[2],cA*ku[3]),
                     pack2h(cA*ku[4],cA*ku[5]), pack2h(cA*ku[6],cA*ku[7]));
    red_add_v4h(dku, pack2h(cA*q[0],cA*q[1]),   pack2h(cA*q[2],cA*q[3]),
                     pack2h(cA*q[4],cA*q[5]),   pack2h(cA*q[6],cA*q[7]));
    red_add_v4h(dkv, pack2h(cB*tp8[0],cB*tp8[1]), pack2h(cB*tp8[2],cB*tp8[3]),
                     pack2h(cB*tp8[4],cB*tp8[5]), pack2h(cB*tp8[6],cB*tp8[7]));
}

// ---------------------------------------------------------------------------
// Memory term
// ---------------------------------------------------------------------------
__global__ void k_mem() {
    int w = (blockIdx.x * 256 + threadIdx.x) >> 5;
    int lane = threadIdx.x & 31;
    if (w >= Nn * Hh) return;
    int n = w >> 1, h = w & 1;
    const float* qm = g_P + (size_t)n * PW + 768 + h * HDm;
    const float* kt = g_KmT + h * HDm * KSL;
    const float* km = g_Km + h * KSL * HDm;
    float2 qv = ((const float2*)qm)[lane];
    float sm = 0.f;
#pragma unroll
    for (int z2 = 0; z2 < 32; z2++) {
        float qa = __shfl_sync(0xffffffffu, qv.x, z2);
        float qb = __shfl_sync(0xffffffffu, qv.y, z2);
        sm += qa * kt[(2 * z2) * KSL + lane] + qb * kt[(2 * z2 + 1) * KSL + lane];
    }
    sm *= 0.125f;
    float e = __expf(sm);
    float Z = wsum32(e);
    float p = e / Z;
    if (lane == 0) g_Lm[w] = logf(Z);
    float a0 = 0.f, a1 = 0.f;
#pragma unroll
    for (int kk = 0; kk < KSL; kk++) {
        float pk = __shfl_sync(0xffffffffu, p, kk);
        a0 += pk * km[kk * HDm + lane];
        a1 += pk * km[kk * HDm + lane + 32];
    }
    __half* du = g_Uh + (size_t)n * PW + 768 + h * HDm;
    du[lane] = __float2half(-0.125f * a0);
    du[lane + 32] = __float2half(-0.125f * a1);
}

// ---------------------------------------------------------------------------
// Launch: R12 fork/join schedule; bwd GEMM fused with final (smem-reuse)
// ---------------------------------------------------------------------------
#define GSMEM (4 * STG_ELEM * 2 * 2)   // 49152 B
extern "C" void kernel_launch(void* const* d_in, const int* in_sizes, int n_in,
                              void* d_out, int out_size) {
    const float* X    = (const float*)d_in[0];
    const int* c2     = (const int*)d_in[1];
    const int* u2     = (const int*)d_in[2];
    const int* c3     = (const int*)d_in[3];
    const int* u3     = (const int*)d_in[4];
    const int* v3     = (const int*)d_in[5];
    const int* tt     = (const int*)d_in[6];
    const int* batch  = (const int*)d_in[7];
    const float* a2   = (const float*)d_in[8];
    const float* step = (const float*)d_in[9];
    const float* gamma= (const float*)d_in[10];
    const float* beta = (const float*)d_in[11];
    const float* WQ2  = (const float*)d_in[12];
    const float* WK2  = (const float*)d_in[13];
    const float* WQ3  = (const float*)d_in[14];
    const float* WK3  = (const float*)d_in[15];
    const float* Ttau = (const float*)d_in[16];
    const float* WQm  = (const float*)d_in[17];
    const float* WKm  = (const float*)d_in[18];
    const float* Bmem = (const float*)d_in[19];
    float* out = (float*)d_out;
    float* Eg  = out + (size_t)Nn * Dd;

    static cudaStream_t s1 = nullptr, s2 = nullptr;
    static cudaEvent_t evA, ev1, ev2, ev3, ev4, ev5;
    if (!s1) {
        cudaStreamCreateWithFlags(&s1, cudaStreamNonBlocking);
        cudaStreamCreateWithFlags(&s2, cudaStreamNonBlocking);
        cudaEventCreateWithFlags(&evA, cudaEventDisableTiming);
        cudaEventCreateWithFlags(&ev1, cudaEventDisableTiming);
        cudaEventCreateWithFlags(&ev2, cudaEventDisableTiming);
        cudaEventCreateWithFlags(&ev3, cudaEventDisableTiming);
        cudaEventCreateWithFlags(&ev4, cudaEventDisableTiming);
        cudaEventCreateWithFlags(&ev5, cudaEventDisableTiming);
        cudaFuncSetAttribute(k_gemmF,
                             cudaFuncAttributeMaxDynamicSharedMemorySize, GSMEM);
        cudaFuncSetAttribute(k_gemmB_fin,
                             cudaFuncAttributeMaxDynamicSharedMemorySize, GSMEM);
    }

    void *pUh, *pZ2, *pZ3, *pGh, *pP, *pPb, *pWcB, *pWcHT;
    cudaGetSymbolAddress(&pUh, g_Uh);
    cudaGetSymbolAddress(&pZ2, g_Z2);
    cudaGetSymbolAddress(&pZ3, g_Z3);
    cudaGetSymbolAddress(&pGh, g_Gh);
    cudaGetSymbolAddress(&pP, g_P);
    cudaGetSymbolAddress(&pPb, g_Pb);
    cudaGetSymbolAddress(&pWcB, g_WcatB);
    cudaGetSymbolAddress(&pWcHT, g_WcatHT);

    // ---- fork ----
    cudaEventRecord(evA, 0);
    cudaStreamWaitEvent(s1, evA, 0);
    cudaStreamWaitEvent(s2, evA, 0);

    // L: LN   |  s1: weights   |  s2: km + memsets
    k_ln<<<Nn / 8, 256>>>(X, gamma, beta);
    k_wcat<<<(PW * Dd + 255) / 256, 256, 0, s1>>>(WQ2, WK2, WQ3, WK3, WQm, Ttau);
    k_km<<<(Hh * KSL * HDm + 255) / 256, 256, 0, s2>>>(Bmem, WKm);
    cudaMemsetAsync(pUh, 0, sizeof(__half) * (size_t)Nn * PW, s2);
    cudaMemsetAsync(pZ2, 0, sizeof(float) * Nn * Hh, s2);
    cudaMemsetAsync(pZ3, 0, sizeof(float) * Nn * Hh, s2);
    cudaMemsetAsync(Eg, 0, sizeof(float) * NGg, s2);
    cudaEventRecord(ev1, s1);
    cudaEventRecord(ev2, s2);

    // L: fwd GEMM (needs ln + wcat), full width, cp.async pipelined
    cudaStreamWaitEvent(0, ev1, 0);
    k_gemmF<<<dim3(PW / 128, Nn / 128), 256, GSMEM>>>(
        (const __nv_bfloat16*)pGh, Dd, (const __nv_bfloat16*)pWcB, Dd,
        (float*)pP, PW, Dd, (__nv_bfloat16*)pPb);
    cudaEventRecord(ev3, 0);

    // s1: pair chain (needs P + Z2/Uh zeroed)
    cudaStreamWaitEvent(s1, ev3, 0);
    cudaStreamWaitEvent(s1, ev2, 0);
    k_pair_fwd<<<Ee / 8, 256, 0, s1>>>(c2, u2, a2);
    k_pair_bwd<<<Ee / 8, 256, 0, s1>>>(c2, u2);
    cudaEventRecord(ev4, s1);

    // s2: motif chain
    cudaStreamWaitEvent(s2, ev3, 0);
    k_motif_fwd<<<Mm / 8, 256, 0, s2>>>(c3, u3, v3, tt, Ttau);
    k_motif_bwd<<<Mm / 8, 256, 0, s2>>>(c3, u3, v3, tt);
    cudaEventRecord(ev5, s2);

    // L: memory term
    cudaStreamWaitEvent(0, ev2, 0);
    k_mem<<<(Nn * Hh) / 8, 256>>>();

    // ---- join ----
    cudaStreamWaitEvent(0, ev4, 0);
    cudaStreamWaitEvent(0, ev5, 0);

    // L: bwd GEMM fused with final update + energy (48KB smem, 2 CTAs/SM)
    k_gemmB_fin<<<dim3(1, Nn / 128), 256, GSMEM>>>(
        (const __half*)pUh, PW, (const __half*)pWcHT, PW, PW,
        X, gamma, step, batch, out, Eg);
}

// round 16
// speedup vs baseline: 1.0581x; 1.0581x over previous
#include <cuda_runtime.h>
#include <cuda_bf16.h>
#include <cuda_fp16.h>
#include <math.h>
#include <stdint.h>

// ---------------------------------------------------------------------------
// Problem constants
// ---------------------------------------------------------------------------
#define Nn   32768
#define Dd   128
#define Hh   2
#define HDm  64
#define Ee   262144
#define Mm   131072
#define NGg  32
#define PW   896          // 128(Q2)+128(K2)+256(Q3)+256(K3)+128(Qm)
#define PB   768          // bf16 mirror width (Q2|K2|Q3|K3)
#define KSL  32
#define TMt  2
#define LAM3 0.5f
#define EPSV 1e-5f

// ---------------------------------------------------------------------------
// Scratch
// ---------------------------------------------------------------------------
__device__ __align__(256) __nv_bfloat16 g_Gh[(size_t)Nn * Dd];  // bf16 LN output
__device__ float g_mu[Nn];
__device__ float g_rstd[Nn];
__device__ float g_P[(size_t)Nn * PW];                          // Qm cols (768..) fp32
__device__ __align__(256) __nv_bfloat16 g_Pb[(size_t)Nn * PB];  // bf16 cols 0..767
__device__ __align__(256) __half g_Uh[(size_t)Nn * PW];         // f16 grad accumulator
__device__ float g_dG[(size_t)Nn * Dd];
__device__ __align__(256) __nv_bfloat16 g_WcatB[PW * Dd];       // bf16 [j][d] fwd GEMM
__device__ __align__(256) __half g_WcatHT[Dd * PW];             // f16 [d][j] bwd GEMM
__device__ __nv_bfloat16 g_TtH[TMt * Hh * 2 * HDm];             // bf16 Ttau mirror
__device__ float g_Km[Hh * KSL * HDm];     // [h][k][z]
__device__ float g_KmT[Hh * HDm * KSL];    // [h][z][k]
__device__ float g_s2[(size_t)Ee * Hh];    // exp(s2)
__device__ float g_Z2[Nn * Hh];
__device__ float g_qk[(size_t)Mm * 4];
__device__ float g_tv[(size_t)Mm * 4];
__device__ float g_s3[(size_t)Mm * Hh];    // exp(s3)
__device__ float g_Z3[Nn * Hh];
__device__ float g_Lm[Nn * Hh];

// ---------------------------------------------------------------------------
// Helpers
// ---------------------------------------------------------------------------
__device__ __forceinline__ float wsum32(float v) {
#pragma unroll
    for (int m = 16; m > 0; m >>= 1) v += __shfl_xor_sync(0xffffffffu, v, m);
    return v;
}
__device__ __forceinline__ float wsum8(float v) {
#pragma unroll
    for (int m = 4; m > 0; m >>= 1) v += __shfl_xor_sync(0xffffffffu, v, m);
    return v;
}
__device__ __forceinline__ void red_add_v4h(__half* addr, uint32_t a, uint32_t b,
                                            uint32_t c, uint32_t d) {
    asm volatile("red.global.add.noftz.v4.f16x2 [%0], {%1, %2, %3, %4};"
                 :: "l"(addr), "r"(a), "r"(b), "r"(c), "r"(d) : "memory");
}
__device__ __forceinline__ uint32_t pack2h(float a, float b) {
    __half2 h = __floats2half2_rn(a, b);
    return *reinterpret_cast<uint32_t*>(&h);
}
__device__ __forceinline__ void ld8bf(const __nv_bfloat16* p, float* f) {
    uint4 r = *(const uint4*)p;
    __nv_bfloat162 h0 = *reinterpret_cast<const __nv_bfloat162*>(&r.x);
    __nv_bfloat162 h1 = *reinterpret_cast<const __nv_bfloat162*>(&r.y);
    __nv_bfloat162 h2 = *reinterpret_cast<const __nv_bfloat162*>(&r.z);
    __nv_bfloat162 h3 = *reinterpret_cast<const __nv_bfloat162*>(&r.w);
    float2 a = __bfloat1622float2(h0), b = __bfloat1622float2(h1);
    float2 c = __bfloat1622float2(h2), d = __bfloat1622float2(h3);
    f[0] = a.x; f[1] = a.y; f[2] = b.x; f[3] = b.y;
    f[4] = c.x; f[5] = c.y; f[6] = d.x; f[7] = d.y;
}
__device__ __forceinline__ void ldsm4(uint32_t* r, uint32_t addr) {
    asm volatile("ldmatrix.sync.aligned.m8n8.x4.shared.b16 {%0,%1,%2,%3}, [%4];"
                 : "=r"(r[0]), "=r"(r[1]), "=r"(r[2]), "=r"(r[3]) : "r"(addr));
}
__device__ __forceinline__ void mma16(float* c, const uint32_t* a, const uint32_t* b, __half) {
    asm volatile(
        "mma.sync.aligned.m16n8k16.row.col.f32.f16.f16.f32 "
        "{%0,%1,%2,%3}, {%4,%5,%6,%7}, {%8,%9}, {%0,%1,%2,%3};"
        : "+f"(c[0]), "+f"(c[1]), "+f"(c[2]), "+f"(c[3])
        : "r"(a[0]), "r"(a[1]), "r"(a[2]), "r"(a[3]), "r"(b[0]), "r"(b[1]));
}
__device__ __forceinline__ void mma16(float* c, const uint32_t* a, const uint32_t* b, __nv_bfloat16) {
    asm volatile(
        "mma.sync.aligned.m16n8k16.row.col.f32.bf16.bf16.f32 "
        "{%0,%1,%2,%3}, {%4,%5,%6,%7}, {%8,%9}, {%0,%1,%2,%3};"
        : "+f"(c[0]), "+f"(c[1]), "+f"(c[2]), "+f"(c[3])
        : "r"(a[0]), "r"(a[1]), "r"(a[2]), "r"(a[3]), "r"(b[0]), "r"(b[1]));
}
#define CP16(dst, src) \
    asm volatile("cp.async.cg.shared.global [%0], [%1], 16;" \
                 :: "r"(dst), "l"(src) : "memory")
#define CP_COMMIT() asm volatile("cp.async.commit_group;" ::: "memory")
#define CP_WAIT4()  asm volatile("cp.async.wait_group 4;" ::: "memory")

// ---------------------------------------------------------------------------
// LayerNorm forward -> bf16 G
// ---------------------------------------------------------------------------
__global__ void k_ln(const float* __restrict__ X, const float* __restrict__ gamma,
                     const float* __restrict__ beta) {
    int w = (blockIdx.x * blockDim.x + threadIdx.x) >> 5;
    int lane = threadIdx.x & 31;
    if (w >= Nn) return;
    const float4 x = *(const float4*)(X + (size_t)w * Dd + lane * 4);
    float s = x.x + x.y + x.z + x.w;
    float mu = wsum32(s) * (1.0f / Dd);
    float4 xc = make_float4(x.x - mu, x.y - mu, x.z - mu, x.w - mu);
    float v = xc.x * xc.x + xc.y * xc.y + xc.z * xc.z + xc.w * xc.w;
    v = wsum32(v) * (1.0f / Dd);
    float rstd = rsqrtf(v + EPSV);
    const float4 g4 = *(const float4*)(gamma + lane * 4);
    const float4 b4 = *(const float4*)(beta + lane * 4);
    float Gx = g4.x * xc.x * rstd + b4.x;
    float Gy = g4.y * xc.y * rstd + b4.y;
    float Gz = g4.z * xc.z * rstd + b4.z;
    float Gw = g4.w * xc.w * rstd + b4.w;
    uint2 pk;
    __nv_bfloat162 h0 = __floats2bfloat162_rn(Gx, Gy);
    __nv_bfloat162 h1 = __floats2bfloat162_rn(Gz, Gw);
    pk.x = *reinterpret_cast<uint32_t*>(&h0);
    pk.y = *reinterpret_cast<uint32_t*>(&h1);
    *(uint2*)(g_Gh + (size_t)w * Dd + lane * 4) = pk;
    if (lane == 0) { g_mu[w] = mu; g_rstd[w] = rstd; }
}

// ---------------------------------------------------------------------------
// Stacked weights + Ttau mirror
// ---------------------------------------------------------------------------
__global__ void k_wcat(const float* __restrict__ WQ2, const float* __restrict__ WK2,
                       const float* __restrict__ WQ3, const float* __restrict__ WK3,
                       const float* __restrict__ WQm, const float* __restrict__ Ttau) {
    int idx = blockIdx.x * blockDim.x + threadIdx.x;
    if (idx < TMt * Hh * 2 * HDm) g_TtH[idx] = __float2bfloat16(Ttau[idx]);
    if (idx >= PW * Dd) return;
    int j = idx / Dd, d = idx - j * Dd;
    float v;
    if (j < 128)      v = WQ2[j * Dd + d];
    else if (j < 256) v = WK2[(j - 128) * Dd + d];
    else if (j < 512) v = WQ3[(j - 256) * Dd + d];
    else if (j < 768) v = WK3[(j - 512) * Dd + d];
    else              v = WQm[(j - 768) * Dd + d];
    g_WcatB[j * Dd + d] = __float2bfloat16(v);
    g_WcatHT[d * PW + j] = __float2half(v);
}

// ---------------------------------------------------------------------------
// Km = B_mem @ W_Km^T per head
// ---------------------------------------------------------------------------
__global__ void k_km(const float* __restrict__ Bm, const float* __restrict__ WKm) {
    int idx = blockIdx.x * blockDim.x + threadIdx.x;
    if (idx >= Hh * KSL * HDm) return;
    int h = idx / (KSL * HDm);
    int k = (idx / HDm) % KSL;
    int z = idx % HDm;
    const float* b = Bm + k * Dd;
    const float* w = WKm + (h * HDm + z) * Dd;
    float acc = 0.f;
#pragma unroll 8
    for (int d = 0; d < Dd; d++) acc += b[d] * w[d];
    g_Km[idx] = acc;
    g_KmT[(h * HDm + z) * KSL + k] = acc;
}

// ---------------------------------------------------------------------------
// Unified 6-stage cp.async pipelined 16-bit GEMM.
// C[M,J] = A[M,K] * Bt[J,K]^T, fp32 accum, m16n8k16 + ldmatrix.
// SPLIT: col0 < PB -> bf16 out to Cb (stride PB); else fp32 out to C.
// Dynamic smem: 6 stages * 2 tiles * 128*24 elems * 2B = 73728 B (2 CTAs/SM).
// ---------------------------------------------------------------------------
#define NSTG 6
#define STG_ELEM (128 * 24)
template<typename T, bool SPLIT>
__global__ void __launch_bounds__(256)
k_gemm16p(const T* __restrict__ A, int lda,
          const T* __restrict__ Bt, int ldb,
          float* __restrict__ C, int ldc, int Kdim,
          __nv_bfloat16* __restrict__ Cb) {
    extern __shared__ __align__(16) char smRaw[];
    T* As = (T*)smRaw;                      // [6][128][24]
    T* Bs = As + NSTG * STG_ELEM;           // [6][128][24]
    int tid = threadIdx.x;
    int warp = tid >> 5, lane = tid & 31;
    int g = lane >> 2, tg = lane & 3;
    int wm = (warp >> 2) * 64;
    int wn = (warp & 3) * 32;
    int row0 = blockIdx.y * 128, col0 = blockIdx.x * 128;
    int lr = tid >> 1;
    int lc = (tid & 1) * 8;
    const T* Ap = A + (size_t)(row0 + lr) * lda + lc;
    const T* Bp = Bt + (size_t)(col0 + lr) * ldb + lc;

    uint32_t aSt[NSTG], bSt[NSTG], aLd[NSTG], bLd[NSTG];
#pragma unroll
    for (int s = 0; s < NSTG; s++) {
        aSt[s] = (uint32_t)__cvta_generic_to_shared(As + (s * 128 + lr) * 24 + lc);
        bSt[s] = (uint32_t)__cvta_generic_to_shared(Bs + (s * 128 + lr) * 24 + lc);
        aLd[s] = (uint32_t)__cvta_generic_to_shared(
            As + (s * 128 + wm + (lane & 15)) * 24 + (lane >> 4) * 8);
        bLd[s] = (uint32_t)__cvta_generic_to_shared(
            Bs + (s * 128 + wn + ((lane >> 4) & 1) * 8 + (lane & 7)) * 24 +
            ((lane >> 3) & 1) * 8);
    }
    const uint32_t pit = 48;                // 24 elems * 2B

    float acc[16][4];
#pragma unroll
    for (int i = 0; i < 16; i++)
#pragma unroll
        for (int j = 0; j < 4; j++) acc[i][j] = 0.f;

    int nk = Kdim >> 4;
#pragma unroll
    for (int s = 0; s < NSTG - 1; s++) {
        if (s < nk) {
            CP16(aSt[s], Ap + s * 16);
            CP16(bSt[s], Bp + s * 16);
        }
        CP_COMMIT();
    }

    int cur = 0;
    for (int kt = 0; kt < nk; kt++) {
        CP_WAIT4();                          // group kt complete
        __syncthreads();
        uint32_t af[4][4], bq[2][4];
#pragma unroll
        for (int mi = 0; mi < 4; mi++)
            ldsm4(af[mi], aLd[cur] + mi * 16 * pit);
#pragma unroll
        for (int ni2 = 0; ni2 < 2; ni2++)
            ldsm4(bq[ni2], bLd[cur] + ni2 * 16 * pit);
#pragma unroll
        for (int mi = 0; mi < 4; mi++)
#pragma unroll
            for (int ni = 0; ni < 4; ni++)
                mma16(acc[mi * 4 + ni], af[mi], &bq[ni >> 1][(ni & 1) * 2], T{});
        int nx = kt + NSTG - 1;
        if (nx < nk) {
            int sl = (cur == 0) ? (NSTG - 1) : (cur - 1);  // (kt+5) % 6
            CP16(aSt[sl], Ap + nx * 16);
            CP16(bSt[sl], Bp + nx * 16);
        }
        CP_COMMIT();
        cur = (cur + 1 == NSTG) ? 0 : cur + 1;
    }

    bool asbf = SPLIT && (col0 < PB);
#pragma unroll
    for (int mi = 0; mi < 4; mi++)
#pragma unroll
        for (int ni = 0; ni < 4; ni++) {
            float* c = acc[mi * 4 + ni];
            int r = row0 + wm + mi * 16 + g;
            int col = col0 + wn + ni * 8 + 2 * tg;
            if (asbf) {
                *(__nv_bfloat162*)(Cb + (size_t)r * PB + col) =
                    __floats2bfloat162_rn(c[0], c[1]);
                *(__nv_bfloat162*)(Cb + (size_t)(r + 8) * PB + col) =
                    __floats2bfloat162_rn(c[2], c[3]);
            } else {
                *(float2*)(C + (size_t)r * ldc + col) = make_float2(c[0], c[1]);
                *(float2*)(C + (size_t)(r + 8) * ldc + col) = make_float2(c[2], c[3]);
            }
        }
}

// ---------------------------------------------------------------------------
// Pair forward: warp handles TWO edges (16 lanes each), 16B gathers.
// ---------------------------------------------------------------------------
__global__ void k_pair_fwd(const int* __restrict__ c2, const int* __restrict__ u2,
                           const float* __restrict__ a2) {
    int w = (blockIdx.x * 256 + threadIdx.x) >> 5;
    int lane = threadIdx.x & 31;
    int e = w * 2 + (lane >> 4);
    if (e >= Ee) return;
    int c = c2[e], u = u2[e];
    int i = lane & 15;                       // 8-col slot within the edge
    float q[8], k[8];
    ld8bf(g_Pb + (size_t)c * PB + i * 8, q);
    ld8bf(g_Pb + (size_t)u * PB + 128 + i * 8, k);
    float part = 0.f;
#pragma unroll
    for (int j = 0; j < 8; j++) part += q[j] * k[j];
    part = wsum8(part);                      // reduce within groups of 8 lanes
    if ((lane & 7) == 0) {
        int h = i >> 3;                      // head: slots 0-7 -> h0, 8-15 -> h1
        float s = part * 0.125f + a2[e * 2 + h];
        float ex = __expf(s);
        g_s2[(size_t)e * 2 + h] = ex;
        atomicAdd(&g_Z2[c * 2 + h], ex);
    }
}

// Pair backward: 16 lanes -> dQ2[c], 16 lanes -> dK2[u]
__global__ void k_pair_bwd(const int* __restrict__ c2, const int* __restrict__ u2) {
    int e = (blockIdx.x * 256 + threadIdx.x) >> 5;
    int lane = threadIdx.x & 31;
    if (e >= Ee) return;
    int c = c2[e], u = u2[e];
    float2 ex = *(const float2*)&g_s2[(size_t)e * 2];
    float2 Z  = *(const float2*)&g_Z2[c * 2];
    float wt0 = -0.125f * ex.x / Z.x;
    float wt1 = -0.125f * ex.y / Z.y;
    int dk_side = lane >> 4;
    int i = lane & 15;
    float wt = (i >> 3) ? wt1 : wt0;
    const __nv_bfloat16* src = dk_side ? (g_Pb + (size_t)c * PB + i * 8)
                                       : (g_Pb + (size_t)u * PB + 128 + i * 8);
    float v[8];
    ld8bf(src, v);
    __half* dst = dk_side ? (g_Uh + (size_t)u * PW + 128 + i * 8)
                          : (g_Uh + (size_t)c * PW + i * 8);
    red_add_v4h(dst, pack2h(wt*v[0],wt*v[1]), pack2h(wt*v[2],wt*v[3]),
                     pack2h(wt*v[4],wt*v[5]), pack2h(wt*v[6],wt*v[7]));
}

// ---------------------------------------------------------------------------
// Motif forward
// ---------------------------------------------------------------------------
__global__ void k_motif_fwd(const int* __restrict__ c3, const int* __restrict__ u3,
                            const int* __restrict__ v3, const int* __restrict__ tt,
                            const float* __restrict__ Ttau) {
    int m = (blockIdx.x * 256 + threadIdx.x) >> 5;
    int lane = threadIdx.x & 31;
    if (m >= Mm) return;
    int c = c3[m], ua = u3[m], vb = v3[m], t = tt[m];
    int off = lane * 8;
    float q[8], ku[8], kv[8];
    ld8bf(g_Pb + (size_t)c  * PB + 256 + off, q);
    ld8bf(g_Pb + (size_t)ua * PB + 512 + off, ku);
    ld8bf(g_Pb + (size_t)vb * PB + 512 + off, kv);
    const float* tp = Ttau + t * 256 + off;
    float qk = 0.f, tv = 0.f;
#pragma unroll
    for (int i = 0; i < 8; i++) {
        qk += q[i] * ku[i];
        tv += tp[i] * kv[i];
    }
    qk = wsum8(qk);
    tv = wsum8(tv);
    int g = lane >> 3;
    if ((lane & 7) == 0) {
        g_qk[(size_t)m * 4 + g] = qk;
        g_tv[(size_t)m * 4 + g] = tv;
    }
    float qk0 = __shfl_sync(0xffffffffu, qk, 0),  tv0 = __shfl_sync(0xffffffffu, tv, 0);
    float qk1 = __shfl_sync(0xffffffffu, qk, 8),  tv1 = __shfl_sync(0xffffffffu, tv, 8);
    float qk2 = __shfl_sync(0xffffffffu, qk, 16), tv2 = __shfl_sync(0xffffffffu, tv, 16);
    float qk3 = __shfl_sync(0xffffffffu, qk, 24), tv3 = __shfl_sync(0xffffffffu, tv, 24);
    if (lane < 2) {
        float s3 = (lane == 0) ? (qk0 * tv0 + qk1 * tv1) * (1.0f / 64)
                               : (qk2 * tv2 + qk3 * tv3) * (1.0f / 64);
        float ex = __expf(s3);
        g_s3[(size_t)m * 2 + lane] = ex;
        atomicAdd(&g_Z3[c * 2 + lane], ex);
    }
}

// Motif backward
__global__ void k_motif_bwd(const int* __restrict__ c3, const int* __restrict__ u3,
                            const int* __restrict__ v3, const int* __restrict__ tt) {
    int m = (blockIdx.x * 256 + threadIdx.x) >> 5;
    int lane = threadIdx.x & 31;
    if (m >= Mm) return;
    int c = c3[m], ua = u3[m], vb = v3[m], t = tt[m];
    int g = lane >> 3;
    int h = g >> 1;
    float2 ex = *(const float2*)&g_s3[(size_t)m * 2];
    float2 Z  = *(const float2*)&g_Z3[c * 2];
    float p = h ? (ex.y / Z.y) : (ex.x / Z.x);
    float gg = -LAM3 * p * (1.0f / 64);
    float cA = gg * g_tv[(size_t)m * 4 + g];
    float cB = gg * g_qk[(size_t)m * 4 + g];
    int off = lane * 8;
    float q[8], ku[8], tp8[8];
    ld8bf(g_Pb + (size_t)c  * PB + 256 + off, q);
    ld8bf(g_Pb + (size_t)ua * PB + 512 + off, ku);
    ld8bf(g_TtH + t * 256 + off, tp8);
    __half* dq  = g_Uh + (size_t)c  * PW + 256 + off;
    __half* dku = g_Uh + (size_t)ua * PW + 512 + off;
    __half* dkv = g_Uh + (size_t)vb * PW + 512 + off;
    red_add_v4h(dq,  pack2h(cA*ku[0],cA*ku[1]), pack2h(cA*ku[2],cA*ku[3]),
                     pack2h(cA*ku[4],cA*ku[5]), pack2h(cA*ku[6],cA*ku[7]));
    red_add_v4h(dku, pack2h(cA*q[0],cA*q[1]),   pack2h(cA*q[2],cA*q[3]),
                     pack2h(cA*q[4],cA*q[5]),   pack2h(cA*q[6],cA*q[7]));
    red_add_v4h(dkv, pack2h(cB*tp8[0],cB*tp8[1]), pack2h(cB*tp8[2],cB*tp8[3]),
                     pack2h(cB*tp8[4],cB*tp8[5]), pack2h(cB*tp8[6],cB*tp8[7]));
}

// ---------------------------------------------------------------------------
// Memory term
// ---------------------------------------------------------------------------
__global__ void k_mem() {
    int w = (blockIdx.x * 256 + threadIdx.x) >> 5;
    int lane = threadIdx.x & 31;
    if (w >= Nn * Hh) return;
    int n = w >> 1, h = w & 1;
    const float* qm = g_P + (size_t)n * PW + 768 + h * HDm;
    const float* kt = g_KmT + h * HDm * KSL;
    const float* km = g_Km + h * KSL * HDm;
    float2 qv = ((const float2*)qm)[lane];
    float sm = 0.f;
#pragma unroll
    for (int z2 = 0; z2 < 32; z2++) {
        float qa = __shfl_sync(0xffffffffu, qv.x, z2);
        float qb = __shfl_sync(0xffffffffu, qv.y, z2);
        sm += qa * kt[(2 * z2) * KSL + lane] + qb * kt[(2 * z2 + 1) * KSL + lane];
    }
    sm *= 0.125f;
    float e = __expf(sm);
    float Z = wsum32(e);
    float p = e / Z;
    if (lane == 0) g_Lm[w] = logf(Z);
    float a0 = 0.f, a1 = 0.f;
#pragma unroll
    for (int kk = 0; kk < KSL; kk++) {
        float pk = __shfl_sync(0xffffffffu, p, kk);
        a0 += pk * km[kk * HDm + lane];
        a1 += pk * km[kk * HDm + lane + 32];
    }
    __half* du = g_Uh + (size_t)n * PW + 768 + h * HDm;
    du[lane] = __float2half(-0.125f * a0);
    du[lane + 32] = __float2half(-0.125f * a1);
}

// ---------------------------------------------------------------------------
// Fused: LN backward + clips + step + per-graph energy
// ---------------------------------------------------------------------------
__global__ void k_final(const float* __restrict__ X, const float* __restrict__ gamma,
                        const float* __restrict__ step, const int* __restrict__ batch,
                        float* __restrict__ out, float* __restrict__ Eg) {
    __shared__ float bins[NGg];
    int tid = threadIdx.x;
    if (tid < NGg) bins[tid] = 0.f;
    __syncthreads();
    int w = (blockIdx.x * blockDim.x + tid) >> 5;
    int lane = tid & 31;
    if (w < Nn) {
        const float4 x = *(const float4*)(X + (size_t)w * Dd + lane * 4);
        const float4 dg = *(const float4*)(g_dG + (size_t)w * Dd + lane * 4);
        const float4 gm = *(const float4*)(gamma + lane * 4);
        float mu = g_mu[w], rstd = g_rstd[w];
        float4 xh = make_float4((x.x - mu) * rstd, (x.y - mu) * rstd,
                                (x.z - mu) * rstd, (x.w - mu) * rstd);
        float4 dxh = make_float4(dg.x * gm.x, dg.y * gm.y, dg.z * gm.z, dg.w * gm.w);
        float S1 = wsum32(dxh.x + dxh.y + dxh.z + dxh.w) * (1.0f / Dd);
        float S2 = wsum32(dxh.x * xh.x + dxh.y * xh.y + dxh.z * xh.z + dxh.w * xh.w) * (1.0f / Dd);
        float ss = wsum32(x.x * x.x + x.y * x.y + x.z * x.z + x.w * x.w);
        float4 g;
        g.x = x.x + rstd * (dxh.x - S1 - xh.x * S2);
        g.y = x.y + rstd * (dxh.y - S1 - xh.y * S2);
        g.z = x.z + rstd * (dxh.z - S1 - xh.z * S2);
        g.w = x.w + rstd * (dxh.w - S1 - xh.w * S2);
        float gss = wsum32(g.x * g.x + g.y * g.y + g.z * g.z + g.w * g.w);
        float sc1 = 1.0f / fmaxf(sqrtf(gss), 1.0f);
        float st = step[0] * sc1;
        float4 xn = make_float4(x.x - st * g.x, x.y - st * g.y,
                                x.z - st * g.z, x.w - st * g.w);
        float sn = wsum32(xn.x * xn.x + xn.y * xn.y + xn.z * xn.z + xn.w * xn.w);
        float sc2 = 10.0f / fmaxf(sqrtf(sn), 10.0f);
        float4 o = make_float4(xn.x * sc2, xn.y * sc2, xn.z * sc2, xn.w * sc2);
        *(float4*)(out + (size_t)w * Dd + lane * 4) = o;
        if (lane == 0) {
            float e = 0.5f * ss;
            float z0 = g_Z2[w * 2], z1 = g_Z2[w * 2 + 1];
            e -= (z0 > 0.f ? logf(z0) : 0.f) + (z1 > 0.f ? logf(z1) : 0.f);
            float y0 = g_Z3[w * 2], y1 = g_Z3[w * 2 + 1];
            e -= LAM3 * ((y0 > 0.f ? logf(y0) : 0.f) + (y1 > 0.f ? logf(y1) : 0.f));
            e -= g_Lm[w * 2] + g_Lm[w * 2 + 1];
            atomicAdd(&bins[batch[w]], e);
        }
    }
    __syncthreads();
    if (tid < NGg) atomicAdd(&Eg[tid], bins[tid]);
}

// ---------------------------------------------------------------------------
// Launch: R12 fork/join schedule + 6-stage cp.async GEMMs
// ---------------------------------------------------------------------------
#define GSMEM (NSTG * STG_ELEM * 2 * 2)   // 73728 B
extern "C" void kernel_launch(void* const* d_in, const int* in_sizes, int n_in,
                              void* d_out, int out_size) {
    const float* X    = (const float*)d_in[0];
    const int* c2     = (const int*)d_in[1];
    const int* u2     = (const int*)d_in[2];
    const int* c3     = (const int*)d_in[3];
    const int* u3     = (const int*)d_in[4];
    const int* v3     = (const int*)d_in[5];
    const int* tt     = (const int*)d_in[6];
    const int* batch  = (const int*)d_in[7];
    const float* a2   = (const float*)d_in[8];
    const float* step = (const float*)d_in[9];
    const float* gamma= (const float*)d_in[10];
    const float* beta = (const float*)d_in[11];
    const float* WQ2  = (const float*)d_in[12];
    const float* WK2  = (const float*)d_in[13];
    const float* WQ3  = (const float*)d_in[14];
    const float* WK3  = (const float*)d_in[15];
    const float* Ttau = (const float*)d_in[16];
    const float* WQm  = (const float*)d_in[17];
    const float* WKm  = (const float*)d_in[18];
    const float* Bmem = (const float*)d_in[19];
    float* out = (float*)d_out;
    float* Eg  = out + (size_t)Nn * Dd;

    static cudaStream_t s1 = nullptr, s2 = nullptr;
    static cudaEvent_t evA, ev1, ev2, ev3, ev4, ev5;
    if (!s1) {
        cudaStreamCreateWithFlags(&s1, cudaStreamNonBlocking);
        cudaStreamCreateWithFlags(&s2, cudaStreamNonBlocking);
        cudaEventCreateWithFlags(&evA, cudaEventDisableTiming);
        cudaEventCreateWithFlags(&ev1, cudaEventDisableTiming);
        cudaEventCreateWithFlags(&ev2, cudaEventDisableTiming);
        cudaEventCreateWithFlags(&ev3, cudaEventDisableTiming);
        cudaEventCreateWithFlags(&ev4, cudaEventDisableTiming);
        cudaEventCreateWithFlags(&ev5, cudaEventDisableTiming);
        cudaFuncSetAttribute(k_gemm16p<__nv_bfloat16, true>,
                             cudaFuncAttributeMaxDynamicSharedMemorySize, GSMEM);
        cudaFuncSetAttribute(k_gemm16p<__half, false>,
                             cudaFuncAttributeMaxDynamicSharedMemorySize, GSMEM);
    }

    void *pUh, *pZ2, *pZ3, *pGh, *pP, *pPb, *pWcB, *pWcHT, *pdG;
    cudaGetSymbolAddress(&pUh, g_Uh);
    cudaGetSymbolAddress(&pZ2, g_Z2);
    cudaGetSymbolAddress(&pZ3, g_Z3);
    cudaGetSymbolAddress(&pGh, g_Gh);
    cudaGetSymbolAddress(&pP, g_P);
    cudaGetSymbolAddress(&pPb, g_Pb);
    cudaGetSymbolAddress(&pWcB, g_WcatB);
    cudaGetSymbolAddress(&pWcHT, g_WcatHT);
    cudaGetSymbolAddress(&pdG, g_dG);

    // ---- fork ----
    cudaEventRecord(evA, 0);
    cudaStreamWaitEvent(s1, evA, 0);
    cudaStreamWaitEvent(s2, evA, 0);

    // L: LN   |  s1: weights   |  s2: km + memsets
    k_ln<<<Nn / 8, 256>>>(X, gamma, beta);
    k_wcat<<<(PW * Dd + 255) / 256, 256, 0, s1>>>(WQ2, WK2, WQ3, WK3, WQm, Ttau);
    k_km<<<(Hh * KSL * HDm + 255) / 256, 256, 0, s2>>>(Bmem, WKm);
    cudaMemsetAsync(pUh, 0, sizeof(__half) * (size_t)Nn * PW, s2);
    cudaMemsetAsync(pZ2, 0, sizeof(float) * Nn * Hh, s2);
    cudaMemsetAsync(pZ3, 0, sizeof(float) * Nn * Hh, s2);
    cudaMemsetAsync(Eg, 0, sizeof(float) * NGg, s2);
    cudaEventRecord(ev1, s1);
    cudaEventRecord(ev2, s2);

    // L: fwd GEMM (needs ln + wcat), full width, 6-stage cp.async
    cudaStreamWaitEvent(0, ev1, 0);
    k_gemm16p<__nv_bfloat16, true><<<dim3(PW / 128, Nn / 128), 256, GSMEM>>>(
        (const __nv_bfloat16*)pGh, Dd, (const __nv_bfloat16*)pWcB, Dd,
        (float*)pP, PW, Dd, (__nv_bfloat16*)pPb);
    cudaEventRecord(ev3, 0);

    // s1: pair chain (needs P + Z2/Uh zeroed)
    cudaStreamWaitEvent(s1, ev3, 0);
    cudaStreamWaitEvent(s1, ev2, 0);
    k_pair_fwd<<<Ee / 16, 256, 0, s1>>>(c2, u2, a2);
    k_pair_bwd<<<Ee / 8, 256, 0, s1>>>(c2, u2);
    cudaEventRecord(ev4, s1);

    // s2: motif chain
    cudaStreamWaitEvent(s2, ev3, 0);
    k_motif_fwd<<<Mm / 8, 256, 0, s2>>>(c3, u3, v3, tt, Ttau);
    k_motif_bwd<<<Mm / 8, 256, 0, s2>>>(c3, u3, v3, tt);
    cudaEventRecord(ev5, s2);

    // L: memory term
    cudaStreamWaitEvent(0, ev2, 0);
    k_mem<<<(Nn * Hh) / 8, 256>>>();

    // ---- join ----
    cudaStreamWaitEvent(0, ev4, 0);
    cudaStreamWaitEvent(0, ev5, 0);

    // L: bwd GEMM (6-stage cp.async) + fused finish
    k_gemm16p<__half, false><<<dim3(Dd / 128, Nn / 128), 256, GSMEM>>>(
        (const __half*)pUh, PW, (const __half*)pWcHT, PW,
        (float*)pdG, Dd, PW, nullptr);
    k_final<<<Nn / 8, 256>>>(X, gamma, step, batch, out, Eg);
}